// round 7
// baseline (speedup 1.0000x reference)
#include <cuda_runtime.h>
#include <cuda_bf16.h>

#define N_NODES_C 500000

// Per-node edge aggregate, float4-padded: one red.global.add.v4.f32 per edge
// (w lane dead but free — REDG path is op-bound, not element-bound).
__device__ float4 g_agg[N_NODES_C];

// ---------------------------------------------------------------------------
__global__ void __launch_bounds__(256) zero_kernel(int n) {
    int i = blockIdx.x * blockDim.x + threadIdx.x;
    if (i < n) g_agg[i] = make_float4(0.f, 0.f, 0.f, 0.f);
}

// ---------------------------------------------------------------------------
// ONE vector RED per edge (one 16B RMW -> one L2 sector op).
__device__ __forceinline__ void red_add3(float* p, float a0, float a1, float a2) {
    asm volatile("red.global.add.v4.f32 [%0], {%1, %2, %3, %4};"
                 :: "l"(p), "f"(a0), "f"(a1), "f"(a2), "f"(0.0f)
                 : "memory");
}

// Scatter: 4 edges per thread, all loads LDG.128. The int64-vs-int32 index
// dtype flag is computed per block from the first 64 values of the base
// edge_index array (row 0 — in-bounds for both dtypes): if the data is really
// int32, an int64 view of random node ids yields values >> N_NODES. This
// replaces a separate detect kernel (was a 4.7us serialized stream bubble).
__global__ void __launch_bounds__(256) scatter_kernel(
    const long long* __restrict__ detect_base,
    const longlong2* __restrict__ t64v,
    const int4*      __restrict__ t32v,
    const float4*    __restrict__ ea4,
    const long long* __restrict__ t64s,
    const int*       __restrict__ t32s,
    const float*     __restrict__ eas,
    int n_quads, int n_edges)
{
    long long dv = __ldg(detect_base + (threadIdx.x & 63));
    int ok = (dv >= 0 && dv < 1000000000LL) ? 1 : 0;
    const bool is64 = (__syncthreads_and(ok) != 0);

    int q = blockIdx.x * blockDim.x + threadIdx.x;
    if (q < n_quads) {
        int i0, i1, i2, i3;
        if (is64) {
            longlong2 a = __ldcs(t64v + 2 * q);
            longlong2 b = __ldcs(t64v + 2 * q + 1);
            i0 = (int)a.x; i1 = (int)a.y; i2 = (int)b.x; i3 = (int)b.y;
        } else {
            int4 a = __ldcs(t32v + q);
            i0 = a.x; i1 = a.y; i2 = a.z; i3 = a.w;
        }
        float4 f0 = __ldcs(ea4 + 3 * q + 0);
        float4 f1 = __ldcs(ea4 + 3 * q + 1);
        float4 f2 = __ldcs(ea4 + 3 * q + 2);
        red_add3((float*)(g_agg + i0), f0.x, f0.y, f0.z);
        red_add3((float*)(g_agg + i1), f0.w, f1.x, f1.y);
        red_add3((float*)(g_agg + i2), f1.z, f1.w, f2.x);
        red_add3((float*)(g_agg + i3), f2.y, f2.z, f2.w);
    }
    int rem = n_edges - n_quads * 4;
    int g = blockIdx.x * blockDim.x + threadIdx.x;
    if (g < rem) {
        int e = n_quads * 4 + g;
        long long t = is64 ? t64s[e] : (long long)t32s[e];
        red_add3((float*)(g_agg + t), eas[3 * e], eas[3 * e + 1], eas[3 * e + 2]);
    }
}

// ---------------------------------------------------------------------------
// Fused MLP (R4 version — fastest measured), 2 nodes/thread, 128-thr blocks.
//   sW1: [50][8] rows = {w0..w4, b1, 0, 0}  -> 2x LDS.128 per j
//   sW2: [50][20] transposed                -> 5x LDS.128 per j (10 pairs)
//   h2 accumulators: 10x f32x2 per node, fma.rn.f32x2.
__global__ void __launch_bounds__(128) mlp_kernel(
    const float4* __restrict__ vattr2,   // two float2 nodes per float4
    const float*  __restrict__ W1, const float* __restrict__ b1,
    const float*  __restrict__ W2, const float* __restrict__ b2,
    const float*  __restrict__ W3, const float* __restrict__ b3,
    float* __restrict__ out, int n_nodes)
{
    __shared__ __align__(16) float sW1[400];   // [50][8]
    __shared__ __align__(16) float sW2[1000];  // [50][20] (W2^T)
    __shared__ __align__(16) float sb2[20];
    __shared__ float sW3[20];
    __shared__ float sb3v;

    for (int t = threadIdx.x; t < 400; t += blockDim.x) {
        int j = t >> 3, k = t & 7;
        float v = 0.0f;
        if (k < 5) v = W1[j * 5 + k];
        else if (k == 5) v = b1[j];
        sW1[t] = v;
    }
    for (int t = threadIdx.x; t < 1000; t += blockDim.x) {
        int j = t / 20, m = t % 20;
        sW2[t] = W2[m * 50 + j];
    }
    {
        int u = threadIdx.x;
        if (u < 20) sb2[u] = b2[u];
        int w = threadIdx.x - 32;
        if (w >= 0 && w < 20) sW3[w] = W3[w];
        if (threadIdx.x == 64) sb3v = b3[0];
    }
    __syncthreads();

    int pair = blockIdx.x * blockDim.x + threadIdx.x;
    int i0 = 2 * pair;
    if (i0 >= n_nodes) return;
    bool has1 = (i0 + 1) < n_nodes;

    float4 vv = __ldg(vattr2 + pair);               // nodes i0, i0+1
    float4 aa = g_agg[i0];
    float4 ab = has1 ? g_agg[i0 + 1] : make_float4(0.f, 0.f, 0.f, 0.f);

    const float xa0 = vv.x, xa1 = vv.y, xa2 = aa.x, xa3 = aa.y, xa4 = aa.z;
    const float xb0 = vv.z, xb1 = vv.w, xb2 = ab.x, xb3 = ab.y, xb4 = ab.z;

    unsigned int w2base = (unsigned int)__cvta_generic_to_shared(sW2);
    unsigned int b2base = (unsigned int)__cvta_generic_to_shared(sb2);
    const float4* sW1v = reinterpret_cast<const float4*>(sW1);

    unsigned long long h2a[10], h2b[10];
    #pragma unroll
    for (int p = 0; p < 5; p++) {
        unsigned long long q0, q1;
        asm("ld.shared.v2.b64 {%0, %1}, [%2];"
            : "=l"(q0), "=l"(q1) : "r"(b2base + p * 16));
        h2a[2 * p] = q0; h2a[2 * p + 1] = q1;
        h2b[2 * p] = q0; h2b[2 * p + 1] = q1;
    }

    #pragma unroll
    for (int j = 0; j < 50; j++) {
        float4 wa = sW1v[j * 2];
        float4 wb = sW1v[j * 2 + 1];   // {w4, b1, 0, 0}

        float sa = wb.y;
        sa = fmaf(wa.x, xa0, sa);
        sa = fmaf(wa.y, xa1, sa);
        sa = fmaf(wa.z, xa2, sa);
        sa = fmaf(wa.w, xa3, sa);
        sa = fmaf(wb.x, xa4, sa);
        sa = fmaxf(sa, 0.0f);

        float sb = wb.y;
        sb = fmaf(wa.x, xb0, sb);
        sb = fmaf(wa.y, xb1, sb);
        sb = fmaf(wa.z, xb2, sb);
        sb = fmaf(wa.w, xb3, sb);
        sb = fmaf(wb.x, xb4, sb);
        sb = fmaxf(sb, 0.0f);

        unsigned long long sda, sdb;
        asm("mov.b64 %0, {%1, %1};" : "=l"(sda) : "f"(sa));
        asm("mov.b64 %0, {%1, %1};" : "=l"(sdb) : "f"(sb));

        unsigned int aj = w2base + j * 80;
        unsigned long long w0, w1_, w2_, w3_, w4, w5, w6, w7, w8, w9;
        asm("ld.shared.v2.b64 {%0, %1}, [%2];"    : "=l"(w0), "=l"(w1_) : "r"(aj));
        asm("ld.shared.v2.b64 {%0, %1}, [%2+16];" : "=l"(w2_), "=l"(w3_) : "r"(aj));
        asm("ld.shared.v2.b64 {%0, %1}, [%2+32];" : "=l"(w4), "=l"(w5) : "r"(aj));
        asm("ld.shared.v2.b64 {%0, %1}, [%2+48];" : "=l"(w6), "=l"(w7) : "r"(aj));
        asm("ld.shared.v2.b64 {%0, %1}, [%2+64];" : "=l"(w8), "=l"(w9) : "r"(aj));

        asm("fma.rn.f32x2 %0, %1, %2, %0;" : "+l"(h2a[0]) : "l"(w0),  "l"(sda));
        asm("fma.rn.f32x2 %0, %1, %2, %0;" : "+l"(h2b[0]) : "l"(w0),  "l"(sdb));
        asm("fma.rn.f32x2 %0, %1, %2, %0;" : "+l"(h2a[1]) : "l"(w1_), "l"(sda));
        asm("fma.rn.f32x2 %0, %1, %2, %0;" : "+l"(h2b[1]) : "l"(w1_), "l"(sdb));
        asm("fma.rn.f32x2 %0, %1, %2, %0;" : "+l"(h2a[2]) : "l"(w2_), "l"(sda));
        asm("fma.rn.f32x2 %0, %1, %2, %0;" : "+l"(h2b[2]) : "l"(w2_), "l"(sdb));
        asm("fma.rn.f32x2 %0, %1, %2, %0;" : "+l"(h2a[3]) : "l"(w3_), "l"(sda));
        asm("fma.rn.f32x2 %0, %1, %2, %0;" : "+l"(h2b[3]) : "l"(w3_), "l"(sdb));
        asm("fma.rn.f32x2 %0, %1, %2, %0;" : "+l"(h2a[4]) : "l"(w4),  "l"(sda));
        asm("fma.rn.f32x2 %0, %1, %2, %0;" : "+l"(h2b[4]) : "l"(w4),  "l"(sdb));
        asm("fma.rn.f32x2 %0, %1, %2, %0;" : "+l"(h2a[5]) : "l"(w5),  "l"(sda));
        asm("fma.rn.f32x2 %0, %1, %2, %0;" : "+l"(h2b[5]) : "l"(w5),  "l"(sdb));
        asm("fma.rn.f32x2 %0, %1, %2, %0;" : "+l"(h2a[6]) : "l"(w6),  "l"(sda));
        asm("fma.rn.f32x2 %0, %1, %2, %0;" : "+l"(h2b[6]) : "l"(w6),  "l"(sdb));
        asm("fma.rn.f32x2 %0, %1, %2, %0;" : "+l"(h2a[7]) : "l"(w7),  "l"(sda));
        asm("fma.rn.f32x2 %0, %1, %2, %0;" : "+l"(h2b[7]) : "l"(w7),  "l"(sdb));
        asm("fma.rn.f32x2 %0, %1, %2, %0;" : "+l"(h2a[8]) : "l"(w8),  "l"(sda));
        asm("fma.rn.f32x2 %0, %1, %2, %0;" : "+l"(h2b[8]) : "l"(w8),  "l"(sdb));
        asm("fma.rn.f32x2 %0, %1, %2, %0;" : "+l"(h2a[9]) : "l"(w9),  "l"(sda));
        asm("fma.rn.f32x2 %0, %1, %2, %0;" : "+l"(h2b[9]) : "l"(w9),  "l"(sdb));
    }

    float oa = sb3v, ob = sb3v;
    #pragma unroll
    for (int p = 0; p < 10; p++) {
        float lo, hi;
        asm("mov.b64 {%0, %1}, %2;" : "=f"(lo), "=f"(hi) : "l"(h2a[p]));
        oa = fmaf(sW3[2 * p],     fmaxf(lo, 0.0f), oa);
        oa = fmaf(sW3[2 * p + 1], fmaxf(hi, 0.0f), oa);
        asm("mov.b64 {%0, %1}, %2;" : "=f"(lo), "=f"(hi) : "l"(h2b[p]));
        ob = fmaf(sW3[2 * p],     fmaxf(lo, 0.0f), ob);
        ob = fmaf(sW3[2 * p + 1], fmaxf(hi, 0.0f), ob);
    }

    if (has1) {
        float2 o2 = make_float2(oa, ob);
        *reinterpret_cast<float2*>(out + i0) = o2;
    } else {
        out[i0] = oa;
    }
}

// ---------------------------------------------------------------------------
extern "C" void kernel_launch(void* const* d_in, const int* in_sizes, int n_in,
                              void* d_out, int out_size) {
    const float*     vattr = (const float*)d_in[0];
    const long long* eidx  = (const long long*)d_in[1];
    const float*     eattr = (const float*)d_in[2];
    const float*     W1    = (const float*)d_in[3];
    const float*     b1    = (const float*)d_in[4];
    const float*     W2    = (const float*)d_in[5];
    const float*     b2    = (const float*)d_in[6];
    const float*     W3    = (const float*)d_in[7];
    const float*     b3    = (const float*)d_in[8];

    int n_nodes = in_sizes[0] / 2;   // vertex_attr: [N, 2]
    int n_edges = in_sizes[2] / 3;   // edge_attr:   [E, 3]

    zero_kernel<<<(n_nodes + 255) / 256, 256>>>(n_nodes);

    const long long* tgt64 = eidx + n_edges;          // row 1 only
    const int*       tgt32 = ((const int*)eidx) + n_edges;

    int n_quads = n_edges / 4;
    int blocks = (n_quads + 255) / 256;
    if (blocks < 1) blocks = 1;
    scatter_kernel<<<blocks, 256>>>(
        eidx,
        (const longlong2*)tgt64, (const int4*)tgt32, (const float4*)eattr,
        tgt64, tgt32, eattr, n_quads, n_edges);

    int n_pairs = (n_nodes + 1) / 2;
    mlp_kernel<<<(n_pairs + 127) / 128, 128>>>(
        (const float4*)vattr, W1, b1, W2, b2, W3, b3,
        (float*)d_out, n_nodes);
}

// round 11
// speedup vs baseline: 1.0321x; 1.0321x over previous
#include <cuda_runtime.h>
#include <cuda_bf16.h>

#define N_NODES_C 500000

// Per-node edge aggregate. Zero-initialized at module load; the MLP kernel
// resets each slot after consuming it, so every invocation (correctness run,
// calibration, timed replays) starts from a zeroed buffer without a separate
// zeroing kernel (was a 4.9us serialized launch).
__device__ float4 g_agg[N_NODES_C];
__device__ int g_idx_is64;

// ---------------------------------------------------------------------------
// int64 vs int32 index detection, parallel (64 concurrent loads). int32 data
// viewed as int64 yields values ~b*2^32 >> N_NODES for random b.
__global__ void detect_kernel(const long long* __restrict__ ei) {
    long long v = ei[threadIdx.x];
    int ok = (v >= 0 && v < 1000000000LL) ? 1 : 0;
    int all = __syncthreads_and(ok);
    if (threadIdx.x == 0) g_idx_is64 = all;
}

// ---------------------------------------------------------------------------
// ONE vector RED per edge: REDG path is op/lane bound, and one 16B RMW hits a
// single 32B L2 sector, so v4 with a dead w-lane beats v2+scalar (R3 lesson).
__device__ __forceinline__ void red_add3(float* p, float a0, float a1, float a2) {
    asm volatile("red.global.add.v4.f32 [%0], {%1, %2, %3, %4};"
                 :: "l"(p), "f"(a0), "f"(a1), "f"(a2), "f"(0.0f)
                 : "memory");
}

// Scatter: 4 edges per thread, all loads LDG.128.
__global__ void __launch_bounds__(256) scatter_kernel(
    const longlong2* __restrict__ t64v,
    const int4*      __restrict__ t32v,
    const float4*    __restrict__ ea4,
    const long long* __restrict__ t64s,
    const int*       __restrict__ t32s,
    const float*     __restrict__ eas,
    int n_quads, int n_edges)
{
    const bool is64 = (g_idx_is64 != 0);
    int q = blockIdx.x * blockDim.x + threadIdx.x;
    if (q < n_quads) {
        int i0, i1, i2, i3;
        if (is64) {
            longlong2 a = __ldcs(t64v + 2 * q);
            longlong2 b = __ldcs(t64v + 2 * q + 1);
            i0 = (int)a.x; i1 = (int)a.y; i2 = (int)b.x; i3 = (int)b.y;
        } else {
            int4 a = __ldcs(t32v + q);
            i0 = a.x; i1 = a.y; i2 = a.z; i3 = a.w;
        }
        float4 f0 = __ldcs(ea4 + 3 * q + 0);
        float4 f1 = __ldcs(ea4 + 3 * q + 1);
        float4 f2 = __ldcs(ea4 + 3 * q + 2);
        red_add3((float*)(g_agg + i0), f0.x, f0.y, f0.z);
        red_add3((float*)(g_agg + i1), f0.w, f1.x, f1.y);
        red_add3((float*)(g_agg + i2), f1.z, f1.w, f2.x);
        red_add3((float*)(g_agg + i3), f2.y, f2.z, f2.w);
    }
    int rem = n_edges - n_quads * 4;
    int g = blockIdx.x * blockDim.x + threadIdx.x;
    if (g < rem) {
        int e = n_quads * 4 + g;
        long long t = is64 ? t64s[e] : (long long)t32s[e];
        red_add3((float*)(g_agg + t), eas[3 * e], eas[3 * e + 1], eas[3 * e + 2]);
    }
}

// ---------------------------------------------------------------------------
// Fused MLP (R4 version — fastest measured), 2 nodes/thread, 128-thr blocks.
//   sW1: [50][8] rows = {w0..w4, b1, 0, 0}  -> 2x LDS.128 per j
//   sW2: [50][20] transposed                -> 5x LDS.128 per j (10 pairs)
//   h2 accumulators: 10x f32x2 per node, fma.rn.f32x2.
// Also resets g_agg[i] = 0 after reading (replaces the zero kernel).
__global__ void __launch_bounds__(128) mlp_kernel(
    const float4* __restrict__ vattr2,   // two float2 nodes per float4
    const float*  __restrict__ W1, const float* __restrict__ b1,
    const float*  __restrict__ W2, const float* __restrict__ b2,
    const float*  __restrict__ W3, const float* __restrict__ b3,
    float* __restrict__ out, int n_nodes)
{
    __shared__ __align__(16) float sW1[400];   // [50][8]
    __shared__ __align__(16) float sW2[1000];  // [50][20] (W2^T)
    __shared__ __align__(16) float sb2[20];
    __shared__ float sW3[20];
    __shared__ float sb3v;

    for (int t = threadIdx.x; t < 400; t += blockDim.x) {
        int j = t >> 3, k = t & 7;
        float v = 0.0f;
        if (k < 5) v = W1[j * 5 + k];
        else if (k == 5) v = b1[j];
        sW1[t] = v;
    }
    for (int t = threadIdx.x; t < 1000; t += blockDim.x) {
        int j = t / 20, m = t % 20;
        sW2[t] = W2[m * 50 + j];
    }
    {
        int u = threadIdx.x;
        if (u < 20) sb2[u] = b2[u];
        int w = threadIdx.x - 32;
        if (w >= 0 && w < 20) sW3[w] = W3[w];
        if (threadIdx.x == 64) sb3v = b3[0];
    }
    __syncthreads();

    int pair = blockIdx.x * blockDim.x + threadIdx.x;
    int i0 = 2 * pair;
    if (i0 >= n_nodes) return;
    bool has1 = (i0 + 1) < n_nodes;

    float4 vv = __ldg(vattr2 + pair);               // nodes i0, i0+1
    float4 aa = g_agg[i0];
    float4 ab = has1 ? g_agg[i0 + 1] : make_float4(0.f, 0.f, 0.f, 0.f);
    // Reset for the next invocation (replaces the zero kernel).
    g_agg[i0] = make_float4(0.f, 0.f, 0.f, 0.f);
    if (has1) g_agg[i0 + 1] = make_float4(0.f, 0.f, 0.f, 0.f);

    const float xa0 = vv.x, xa1 = vv.y, xa2 = aa.x, xa3 = aa.y, xa4 = aa.z;
    const float xb0 = vv.z, xb1 = vv.w, xb2 = ab.x, xb3 = ab.y, xb4 = ab.z;

    unsigned int w2base = (unsigned int)__cvta_generic_to_shared(sW2);
    unsigned int b2base = (unsigned int)__cvta_generic_to_shared(sb2);
    const float4* sW1v = reinterpret_cast<const float4*>(sW1);

    unsigned long long h2a[10], h2b[10];
    #pragma unroll
    for (int p = 0; p < 5; p++) {
        unsigned long long q0, q1;
        asm("ld.shared.v2.b64 {%0, %1}, [%2];"
            : "=l"(q0), "=l"(q1) : "r"(b2base + p * 16));
        h2a[2 * p] = q0; h2a[2 * p + 1] = q1;
        h2b[2 * p] = q0; h2b[2 * p + 1] = q1;
    }

    #pragma unroll
    for (int j = 0; j < 50; j++) {
        float4 wa = sW1v[j * 2];
        float4 wb = sW1v[j * 2 + 1];   // {w4, b1, 0, 0}

        float sa = wb.y;
        sa = fmaf(wa.x, xa0, sa);
        sa = fmaf(wa.y, xa1, sa);
        sa = fmaf(wa.z, xa2, sa);
        sa = fmaf(wa.w, xa3, sa);
        sa = fmaf(wb.x, xa4, sa);
        sa = fmaxf(sa, 0.0f);

        float sb = wb.y;
        sb = fmaf(wa.x, xb0, sb);
        sb = fmaf(wa.y, xb1, sb);
        sb = fmaf(wa.z, xb2, sb);
        sb = fmaf(wa.w, xb3, sb);
        sb = fmaf(wb.x, xb4, sb);
        sb = fmaxf(sb, 0.0f);

        unsigned long long sda, sdb;
        asm("mov.b64 %0, {%1, %1};" : "=l"(sda) : "f"(sa));
        asm("mov.b64 %0, {%1, %1};" : "=l"(sdb) : "f"(sb));

        unsigned int aj = w2base + j * 80;
        unsigned long long w0, w1_, w2_, w3_, w4, w5, w6, w7, w8, w9;
        asm("ld.shared.v2.b64 {%0, %1}, [%2];"    : "=l"(w0), "=l"(w1_) : "r"(aj));
        asm("ld.shared.v2.b64 {%0, %1}, [%2+16];" : "=l"(w2_), "=l"(w3_) : "r"(aj));
        asm("ld.shared.v2.b64 {%0, %1}, [%2+32];" : "=l"(w4), "=l"(w5) : "r"(aj));
        asm("ld.shared.v2.b64 {%0, %1}, [%2+48];" : "=l"(w6), "=l"(w7) : "r"(aj));
        asm("ld.shared.v2.b64 {%0, %1}, [%2+64];" : "=l"(w8), "=l"(w9) : "r"(aj));

        asm("fma.rn.f32x2 %0, %1, %2, %0;" : "+l"(h2a[0]) : "l"(w0),  "l"(sda));
        asm("fma.rn.f32x2 %0, %1, %2, %0;" : "+l"(h2b[0]) : "l"(w0),  "l"(sdb));
        asm("fma.rn.f32x2 %0, %1, %2, %0;" : "+l"(h2a[1]) : "l"(w1_), "l"(sda));
        asm("fma.rn.f32x2 %0, %1, %2, %0;" : "+l"(h2b[1]) : "l"(w1_), "l"(sdb));
        asm("fma.rn.f32x2 %0, %1, %2, %0;" : "+l"(h2a[2]) : "l"(w2_), "l"(sda));
        asm("fma.rn.f32x2 %0, %1, %2, %0;" : "+l"(h2b[2]) : "l"(w2_), "l"(sdb));
        asm("fma.rn.f32x2 %0, %1, %2, %0;" : "+l"(h2a[3]) : "l"(w3_), "l"(sda));
        asm("fma.rn.f32x2 %0, %1, %2, %0;" : "+l"(h2b[3]) : "l"(w3_), "l"(sdb));
        asm("fma.rn.f32x2 %0, %1, %2, %0;" : "+l"(h2a[4]) : "l"(w4),  "l"(sda));
        asm("fma.rn.f32x2 %0, %1, %2, %0;" : "+l"(h2b[4]) : "l"(w4),  "l"(sdb));
        asm("fma.rn.f32x2 %0, %1, %2, %0;" : "+l"(h2a[5]) : "l"(w5),  "l"(sda));
        asm("fma.rn.f32x2 %0, %1, %2, %0;" : "+l"(h2b[5]) : "l"(w5),  "l"(sdb));
        asm("fma.rn.f32x2 %0, %1, %2, %0;" : "+l"(h2a[6]) : "l"(w6),  "l"(sda));
        asm("fma.rn.f32x2 %0, %1, %2, %0;" : "+l"(h2b[6]) : "l"(w6),  "l"(sdb));
        asm("fma.rn.f32x2 %0, %1, %2, %0;" : "+l"(h2a[7]) : "l"(w7),  "l"(sda));
        asm("fma.rn.f32x2 %0, %1, %2, %0;" : "+l"(h2b[7]) : "l"(w7),  "l"(sdb));
        asm("fma.rn.f32x2 %0, %1, %2, %0;" : "+l"(h2a[8]) : "l"(w8),  "l"(sda));
        asm("fma.rn.f32x2 %0, %1, %2, %0;" : "+l"(h2b[8]) : "l"(w8),  "l"(sdb));
        asm("fma.rn.f32x2 %0, %1, %2, %0;" : "+l"(h2a[9]) : "l"(w9),  "l"(sda));
        asm("fma.rn.f32x2 %0, %1, %2, %0;" : "+l"(h2b[9]) : "l"(w9),  "l"(sdb));
    }

    float oa = sb3v, ob = sb3v;
    #pragma unroll
    for (int p = 0; p < 10; p++) {
        float lo, hi;
        asm("mov.b64 {%0, %1}, %2;" : "=f"(lo), "=f"(hi) : "l"(h2a[p]));
        oa = fmaf(sW3[2 * p],     fmaxf(lo, 0.0f), oa);
        oa = fmaf(sW3[2 * p + 1], fmaxf(hi, 0.0f), oa);
        asm("mov.b64 {%0, %1}, %2;" : "=f"(lo), "=f"(hi) : "l"(h2b[p]));
        ob = fmaf(sW3[2 * p],     fmaxf(lo, 0.0f), ob);
        ob = fmaf(sW3[2 * p + 1], fmaxf(hi, 0.0f), ob);
    }

    if (has1) {
        float2 o2 = make_float2(oa, ob);
        *reinterpret_cast<float2*>(out + i0) = o2;
    } else {
        out[i0] = oa;
    }
}

// ---------------------------------------------------------------------------
extern "C" void kernel_launch(void* const* d_in, const int* in_sizes, int n_in,
                              void* d_out, int out_size) {
    const float*     vattr = (const float*)d_in[0];
    const long long* eidx  = (const long long*)d_in[1];
    const float*     eattr = (const float*)d_in[2];
    const float*     W1    = (const float*)d_in[3];
    const float*     b1    = (const float*)d_in[4];
    const float*     W2    = (const float*)d_in[5];
    const float*     b2    = (const float*)d_in[6];
    const float*     W3    = (const float*)d_in[7];
    const float*     b3    = (const float*)d_in[8];

    int n_nodes = in_sizes[0] / 2;   // vertex_attr: [N, 2]
    int n_edges = in_sizes[2] / 3;   // edge_attr:   [E, 3]

    detect_kernel<<<1, 64>>>(eidx);

    const long long* tgt64 = eidx + n_edges;          // row 1 only
    const int*       tgt32 = ((const int*)eidx) + n_edges;

    int n_quads = n_edges / 4;
    int blocks = (n_quads + 255) / 256;
    if (blocks < 1) blocks = 1;
    scatter_kernel<<<blocks, 256>>>(
        (const longlong2*)tgt64, (const int4*)tgt32, (const float4*)eattr,
        tgt64, tgt32, eattr, n_quads, n_edges);

    int n_pairs = (n_nodes + 1) / 2;
    mlp_kernel<<<(n_pairs + 127) / 128, 128>>>(
        (const float4*)vattr, W1, b1, W2, b2, W3, b3,
        (float*)d_out, n_nodes);
}